// round 6
// baseline (speedup 1.0000x reference)
#include <cuda_runtime.h>

typedef unsigned long long ull;

#define NROWS 4194304
#define NGRP  (NROWS/4)
#define NBLK  148
#define NTHR  512
#define TT    (NBLK*NTHR)
#define NWARP (NTHR/32)

// 80 MB activation scratch, SoA: g_Z[f*NROWS + row]
__device__ float g_Z[(size_t)5 * NROWS];
// per-round block partial sums (double-buffered by round parity)
__device__ float g_part[2][NBLK * 20];
__device__ unsigned g_cnt = 0;
__device__ unsigned g_gen = 0;

// ---------------- packed f32x2 helpers ----------------
__device__ __forceinline__ ull pk(float lo, float hi) {
    ull r; asm("mov.b64 %0,{%1,%2};" : "=l"(r) : "f"(lo), "f"(hi)); return r;
}
__device__ __forceinline__ void upk(ull v, float& lo, float& hi) {
    asm("mov.b64 {%0,%1},%2;" : "=f"(lo), "=f"(hi) : "l"(v));
}
__device__ __forceinline__ ull fma2(ull a, ull b, ull c) {
    ull d; asm("fma.rn.f32x2 %0,%1,%2,%3;" : "=l"(d) : "l"(a), "l"(b), "l"(c)); return d;
}
__device__ __forceinline__ ull add2(ull a, ull b) {
    ull d; asm("add.rn.f32x2 %0,%1,%2;" : "=l"(d) : "l"(a), "l"(b)); return d;
}
__device__ __forceinline__ ull relu2(ull a) {
    float lo, hi; upk(a, lo, hi);
    return pk(fmaxf(lo, 0.f), fmaxf(hi, 0.f));
}

// ---------------- grid barrier (generation counter, replay-safe) ----------------
// __threadfence() (gpu scope) emits CCTL.IVALL on sm_103a -> L1D invalidated,
// so post-barrier reads of other blocks' data are coherent.
__device__ __forceinline__ void grid_barrier() {
    __threadfence();
    __syncthreads();
    if (threadIdx.x == 0) {
        unsigned my = *((volatile unsigned*)&g_gen);
        unsigned t = atomicAdd(&g_cnt, 1u);
        if (t == (unsigned)(NBLK - 1)) {
            g_cnt = 0u;
            __threadfence();
            atomicAdd(&g_gen, 1u);
        } else {
            while (*((volatile unsigned*)&g_gen) == my) { __nanosleep(64); }
        }
    }
    __syncthreads();
    __threadfence();
}

// ---------------- Z load/store (two packed row-pairs = 4 rows) ----------------
__device__ __forceinline__ void loadZ2(int g, ull a[5], ull b[5]) {
#pragma unroll
    for (int f = 0; f < 5; f++) {
        ulonglong2 v = *(const ulonglong2*)&g_Z[(size_t)f * NROWS + 4 * (size_t)g];
        a[f] = v.x; b[f] = v.y;
    }
}
__device__ __forceinline__ void storeZ2(int g, const ull a[5], const ull b[5]) {
#pragma unroll
    for (int f = 0; f < 5; f++) {
        ulonglong2 v; v.x = a[f]; v.y = b[f];
        *(ulonglong2*)&g_Z[(size_t)f * NROWS + 4 * (size_t)g] = v;
    }
}

// ---------------- stats accumulation: 5 means + 15 upper-tri 2nd moments ----------------
__device__ __forceinline__ void st2(ull acc[20], const ull p[5]) {
#pragma unroll
    for (int i = 0; i < 5; i++) acc[i] = add2(acc[i], p[i]);
    int c = 5;
#pragma unroll
    for (int i = 0; i < 5; i++) {
#pragma unroll
        for (int k = i; k < 5; k++) { acc[c] = fma2(p[i], p[k], acc[c]); c++; }
    }
}

// h = relu(W z + b) for a packed pair
__device__ __forceinline__ void aff5r(const ull* sW, const ull* sB, const ull in[5], ull out[5]) {
#pragma unroll
    for (int j = 0; j < 5; j++) {
        ull t = sB[j];
#pragma unroll
        for (int i = 0; i < 5; i++) t = fma2(sW[j * 5 + i], in[i], t);
        out[j] = relu2(t);
    }
}

// ---------------- deterministic block reduction -> g_part[slot] ----------------
__device__ __forceinline__ void reduce_store(ull acc[20], int slot, float (*swr)[20]) {
    int tid = threadIdx.x;
    float a[20];
#pragma unroll
    for (int j = 0; j < 20; j++) { float lo, hi; upk(acc[j], lo, hi); a[j] = lo + hi; }
#pragma unroll
    for (int j = 0; j < 20; j++) {
#pragma unroll
        for (int o = 16; o > 0; o >>= 1) a[j] += __shfl_down_sync(0xffffffffu, a[j], o);
    }
    int w = tid >> 5, l = tid & 31;
    if (l == 0) {
#pragma unroll
        for (int j = 0; j < 20; j++) swr[w][j] = a[j];
    }
    __syncthreads();
    if (tid < 20) {
        float t = 0.f;
#pragma unroll
        for (int k = 0; k < NWARP; k++) t += swr[k][tid];
        g_part[slot][blockIdx.x * 20 + tid] = t;
    }
}

// ---------------- BN fold: exact affine from input stats ----------------
// y = Wz+b ; mu_j = w_j.m + b_j ; var_j = w_j^T C w_j , C = S/N - m m^T (biased)
// effW = W * rstd * g ; effB = (b - mu) * rstd * g + beta
__device__ __forceinline__ void fold_affine(
    int slot, int J,
    const float* __restrict__ W, const float* __restrict__ B,
    const float* __restrict__ G, const float* __restrict__ Bt,
    ull* sW, ull* sB, float* sS)
{
    int tid = threadIdx.x;
    if (tid < 20) {
        float t = 0.f;
        for (int k = 0; k < NBLK; k++) t += g_part[slot][k * 20 + tid];
        sS[tid] = t;
    }
    __syncthreads();
    if (tid < J) {
        const double inv = 1.0 / (double)NROWS;
        double m[5], w[5];
#pragma unroll
        for (int i = 0; i < 5; i++) { m[i] = (double)sS[i] * inv; w[i] = (double)W[tid * 5 + i]; }
        double mu = (double)B[tid];
#pragma unroll
        for (int i = 0; i < 5; i++) mu += w[i] * m[i];
        double var = 0.0; int c = 5;
        for (int i = 0; i < 5; i++)
            for (int k = i; k < 5; k++) {
                double C = (double)sS[c] * inv - m[i] * m[k];
                var += (i == k ? w[i] * w[k] : 2.0 * w[i] * w[k]) * C;
                c++;
            }
        double rstd = rsqrt(var + 1e-5);
        float sc = (float)((double)G[tid] * rstd);
#pragma unroll
        for (int i = 0; i < 5; i++) { float wv = W[tid * 5 + i] * sc; sW[tid * 5 + i] = pk(wv, wv); }
        float bv = (float)(((double)B[tid] - mu) * rstd * (double)G[tid] + (double)Bt[tid]);
        sB[tid] = pk(bv, bv);
    }
    __syncthreads();
}

// ---------------- the whole net in one persistent kernel ----------------
__global__ void __launch_bounds__(NTHR, 1) net_kernel(
    const float* __restrict__ x,
    const float* __restrict__ lw,  const float* __restrict__ lb,
    const float* __restrict__ skw, const float* __restrict__ skb,
    const float* __restrict__ bng, const float* __restrict__ bnb,
    const float* __restrict__ l9w, const float* __restrict__ l9b,
    const float* __restrict__ b9g, const float* __restrict__ b9b,
    const float* __restrict__ l10w, const float* __restrict__ l10b,
    float* __restrict__ out)
{
    __shared__ ull sWi[25], sBi[5], sWj[25], sBj[5], sSkW[25];
    __shared__ float swr[NWARP][20];
    __shared__ float sS[20];

    const int tid = threadIdx.x;
    const int gt0 = blockIdx.x * NTHR + tid;

    ull acc[20];

    // ---- pass 0: transpose x (AoS) -> g_Z (SoA) + stats(x) -> slot 0
#pragma unroll
    for (int q = 0; q < 20; q++) acc[q] = 0ull;
    for (int g = gt0; g < NGRP; g += TT) {
        const float4* p = (const float4*)(x + (size_t)20 * g);
        float4 A = p[0], Bq = p[1], Cq = p[2], Dq = p[3], Eq = p[4];
        ull a[5], b[5];
        a[0] = pk(A.x,  Bq.y); a[1] = pk(A.y,  Bq.z); a[2] = pk(A.z,  Bq.w);
        a[3] = pk(A.w,  Cq.x); a[4] = pk(Bq.x, Cq.y);
        b[0] = pk(Cq.z, Dq.w); b[1] = pk(Cq.w, Eq.x); b[2] = pk(Dq.x, Eq.y);
        b[3] = pk(Dq.y, Eq.z); b[4] = pk(Dq.z, Eq.w);
        storeZ2(g, a, b);
        st2(acc, a); st2(acc, b);
    }
    reduce_store(acc, 0, swr);
    grid_barrier();

    int slot = 0;
    for (int blk = 0; blk < 4; blk++) {
        const int li = 2 * blk, lj = li + 1;
        fold_affine(slot, 5, lw + li * 25, lb + li * 5, bng + li * 5, bnb + li * 5, sWi, sBi, sS);
        slot ^= 1;
        // ---- pass 1: stats(h), h not materialized
#pragma unroll
        for (int q = 0; q < 20; q++) acc[q] = 0ull;
        for (int g = gt0; g < NGRP; g += TT) {
            ull za[5], zb[5], ha[5], hb[5];
            loadZ2(g, za, zb);
            aff5r(sWi, sBi, za, ha);
            aff5r(sWi, sBi, zb, hb);
            st2(acc, ha); st2(acc, hb);
        }
        reduce_store(acc, slot, swr);
        grid_barrier();
        fold_affine(slot, 5, lw + lj * 25, lb + lj * 5, bng + lj * 5, bnb + lj * 5, sWj, sBj, sS);
        if (tid < 25) { float w = skw[blk * 25 + tid]; sSkW[tid] = pk(w, w); }
        if (tid < 5)  { float sb = skb[blk * 5 + tid]; sBj[tid] = add2(sBj[tid], pk(sb, sb)); }
        __syncthreads();
        slot ^= 1;
        // ---- pass 2: z' = relu(foldaff_j(recompute h) + skip(z)), write Z, stats(z')
#pragma unroll
        for (int q = 0; q < 20; q++) acc[q] = 0ull;
        for (int g = gt0; g < NGRP; g += TT) {
            ull za[5], zb[5], ha[5], hb[5], na[5], nb[5];
            loadZ2(g, za, zb);
            aff5r(sWi, sBi, za, ha);
            aff5r(sWi, sBi, zb, hb);
#pragma unroll
            for (int o = 0; o < 5; o++) {
                ull ta = sBj[o], tb = sBj[o];
#pragma unroll
                for (int i2 = 0; i2 < 5; i2++) {
                    ta = fma2(sWj[o * 5 + i2], ha[i2], ta);
                    tb = fma2(sWj[o * 5 + i2], hb[i2], tb);
                }
#pragma unroll
                for (int i2 = 0; i2 < 5; i2++) {
                    ta = fma2(sSkW[o * 5 + i2], za[i2], ta);
                    tb = fma2(sSkW[o * 5 + i2], zb[i2], tb);
                }
                na[o] = relu2(ta); nb[o] = relu2(tb);
            }
            storeZ2(g, na, nb);
            st2(acc, na); st2(acc, nb);
        }
        reduce_store(acc, slot, swr);
        grid_barrier();
    }

    // ---- final: fold lin9+bn9 from stats(z), then out = lin10(relu(...))
    fold_affine(slot, 2, l9w, l9b, b9g, b9b, sWi, sBi, sS);
    const float w0 = l10w[0], w1 = l10w[1], c10 = l10b[0];
    const ull W0 = pk(w0, w0), W1 = pk(w1, w1), B10 = pk(c10, c10);
    for (int g = gt0; g < NGRP; g += TT) {
        ull za[5], zb[5];
        loadZ2(g, za, zb);
        ull q0a = sBi[0], q1a = sBi[1], q0b = sBi[0], q1b = sBi[1];
#pragma unroll
        for (int i2 = 0; i2 < 5; i2++) {
            q0a = fma2(sWi[0 * 5 + i2], za[i2], q0a);
            q1a = fma2(sWi[1 * 5 + i2], za[i2], q1a);
            q0b = fma2(sWi[0 * 5 + i2], zb[i2], q0b);
            q1b = fma2(sWi[1 * 5 + i2], zb[i2], q1b);
        }
        q0a = relu2(q0a); q1a = relu2(q1a); q0b = relu2(q0b); q1b = relu2(q1b);
        ull oa = fma2(W0, q0a, fma2(W1, q1a, B10));
        ull ob = fma2(W0, q0b, fma2(W1, q1b, B10));
        float o0, o1, o2, o3; upk(oa, o0, o1); upk(ob, o2, o3);
        *(float4*)&out[4 * (size_t)g] = make_float4(o0, o1, o2, o3);
    }
}

extern "C" void kernel_launch(void* const* d_in, const int* in_sizes, int n_in,
                              void* d_out, int out_size) {
    (void)in_sizes; (void)n_in; (void)out_size;
    net_kernel<<<NBLK, NTHR>>>(
        (const float*)d_in[0],   // x
        (const float*)d_in[1],   // lins_w
        (const float*)d_in[2],   // lins_b
        (const float*)d_in[3],   // skips_w
        (const float*)d_in[4],   // skips_b
        (const float*)d_in[5],   // bn_g
        (const float*)d_in[6],   // bn_b
        (const float*)d_in[7],   // lin9_w
        (const float*)d_in[8],   // lin9_b
        (const float*)d_in[9],   // bn9_g
        (const float*)d_in[10],  // bn9_b
        (const float*)d_in[11],  // lin10_w
        (const float*)d_in[12],  // lin10_b
        (float*)d_out);
}

// round 10
// speedup vs baseline: 2.5702x; 2.5702x over previous
#include <cuda_runtime.h>

typedef unsigned long long ull;

#define NROWS 4194304
#define NGRP  (NROWS/4)
#define NBLK  148
#define NTHR  512
#define TT    (NBLK*NTHR)
#define NWARP (NTHR/32)

// 80 MB activation scratch, SoA: g_Z[f*NROWS + row]
__device__ float g_Z[(size_t)5 * NROWS];
// per-round block partial sums (double-buffered by round parity)
__device__ float g_part[2][NBLK * 20];
__device__ unsigned g_cnt = 0;
__device__ unsigned g_gen = 0;

// ---------------- packed f32x2 helpers ----------------
__device__ __forceinline__ ull pk(float lo, float hi) {
    ull r; asm("mov.b64 %0,{%1,%2};" : "=l"(r) : "f"(lo), "f"(hi)); return r;
}
__device__ __forceinline__ void upk(ull v, float& lo, float& hi) {
    asm("mov.b64 {%0,%1},%2;" : "=f"(lo), "=f"(hi) : "l"(v));
}
__device__ __forceinline__ ull fma2(ull a, ull b, ull c) {
    ull d; asm("fma.rn.f32x2 %0,%1,%2,%3;" : "=l"(d) : "l"(a), "l"(b), "l"(c)); return d;
}
__device__ __forceinline__ ull add2(ull a, ull b) {
    ull d; asm("add.rn.f32x2 %0,%1,%2;" : "=l"(d) : "l"(a), "l"(b)); return d;
}
__device__ __forceinline__ ull relu2(ull a) {
    float lo, hi; upk(a, lo, hi);
    return pk(fmaxf(lo, 0.f), fmaxf(hi, 0.f));
}

// ---------------- L2 cache policies (policy-operand form: width-agnostic) ----------------
__device__ __forceinline__ ull mkpolicy_evict_last() {
    ull p; asm("createpolicy.fractional.L2::evict_last.b64 %0, 1.0;" : "=l"(p)); return p;
}
__device__ __forceinline__ ull mkpolicy_evict_first() {
    ull p; asm("createpolicy.fractional.L2::evict_first.b64 %0, 1.0;" : "=l"(p)); return p;
}

// ---------------- grid barrier (generation counter, replay-safe) ----------------
__device__ __forceinline__ void grid_barrier() {
    __threadfence();
    __syncthreads();
    if (threadIdx.x == 0) {
        unsigned my = *((volatile unsigned*)&g_gen);
        unsigned t = atomicAdd(&g_cnt, 1u);
        if (t == (unsigned)(NBLK - 1)) {
            g_cnt = 0u;
            __threadfence();
            atomicAdd(&g_gen, 1u);
        } else {
            while (*((volatile unsigned*)&g_gen) == my) { __nanosleep(64); }
        }
    }
    __syncthreads();
    __threadfence();
}

// ---------------- Z load/store, pinned to L2 via evict_last policy ----------------
__device__ __forceinline__ void loadZ2(int g, ull a[5], ull b[5], ull pol) {
#pragma unroll
    for (int f = 0; f < 5; f++) {
        const ull* p = (const ull*)&g_Z[(size_t)f * NROWS + 4 * (size_t)g];
        asm volatile("ld.global.L2::cache_hint.v2.u64 {%0,%1}, [%2], %3;"
                     : "=l"(a[f]), "=l"(b[f]) : "l"(p), "l"(pol));
    }
}
__device__ __forceinline__ void storeZ2(int g, const ull a[5], const ull b[5], ull pol) {
#pragma unroll
    for (int f = 0; f < 5; f++) {
        ull* p = (ull*)&g_Z[(size_t)f * NROWS + 4 * (size_t)g];
        asm volatile("st.global.L2::cache_hint.v2.u64 [%0], {%1,%2}, %3;"
                     :: "l"(p), "l"(a[f]), "l"(b[f]), "l"(pol) : "memory");
    }
}
// one-shot input read: don't pollute L2
__device__ __forceinline__ float4 load_x4_stream(const float4* p, ull pol) {
    float4 v;
    asm volatile("ld.global.nc.L2::cache_hint.v4.f32 {%0,%1,%2,%3}, [%4], %5;"
                 : "=f"(v.x), "=f"(v.y), "=f"(v.z), "=f"(v.w) : "l"(p), "l"(pol));
    return v;
}

// ---------------- stats accumulation: 5 means + 15 upper-tri 2nd moments ----------------
__device__ __forceinline__ void st2(ull acc[20], const ull p[5]) {
#pragma unroll
    for (int i = 0; i < 5; i++) acc[i] = add2(acc[i], p[i]);
    int c = 5;
#pragma unroll
    for (int i = 0; i < 5; i++) {
#pragma unroll
        for (int k = i; k < 5; k++) { acc[c] = fma2(p[i], p[k], acc[c]); c++; }
    }
}

// h = relu(W z + b) for a packed pair
__device__ __forceinline__ void aff5r(const ull* sW, const ull* sB, const ull in[5], ull out[5]) {
#pragma unroll
    for (int j = 0; j < 5; j++) {
        ull t = sB[j];
#pragma unroll
        for (int i = 0; i < 5; i++) t = fma2(sW[j * 5 + i], in[i], t);
        out[j] = relu2(t);
    }
}

// ---------------- deterministic block reduction -> g_part[slot] ----------------
__device__ __forceinline__ void reduce_store(ull acc[20], int slot, float (*swr)[20]) {
    int tid = threadIdx.x;
    float a[20];
#pragma unroll
    for (int j = 0; j < 20; j++) { float lo, hi; upk(acc[j], lo, hi); a[j] = lo + hi; }
#pragma unroll
    for (int j = 0; j < 20; j++) {
#pragma unroll
        for (int o = 16; o > 0; o >>= 1) a[j] += __shfl_down_sync(0xffffffffu, a[j], o);
    }
    int w = tid >> 5, l = tid & 31;
    if (l == 0) {
#pragma unroll
        for (int j = 0; j < 20; j++) swr[w][j] = a[j];
    }
    __syncthreads();
    if (tid < 20) {
        float t = 0.f;
#pragma unroll
        for (int k = 0; k < NWARP; k++) t += swr[k][tid];
        g_part[slot][blockIdx.x * 20 + tid] = t;
    }
}

// ---------------- BN fold: exact affine from input stats ----------------
__device__ __forceinline__ void fold_affine(
    int slot, int J,
    const float* __restrict__ W, const float* __restrict__ B,
    const float* __restrict__ G, const float* __restrict__ Bt,
    ull* sW, ull* sB, float* sS)
{
    int tid = threadIdx.x;
    if (tid < 20) {
        float t = 0.f;
        for (int k = 0; k < NBLK; k++) t += g_part[slot][k * 20 + tid];
        sS[tid] = t;
    }
    __syncthreads();
    if (tid < J) {
        const double inv = 1.0 / (double)NROWS;
        double m[5], w[5];
#pragma unroll
        for (int i = 0; i < 5; i++) { m[i] = (double)sS[i] * inv; w[i] = (double)W[tid * 5 + i]; }
        double mu = (double)B[tid];
#pragma unroll
        for (int i = 0; i < 5; i++) mu += w[i] * m[i];
        double var = 0.0; int c = 5;
        for (int i = 0; i < 5; i++)
            for (int k = i; k < 5; k++) {
                double C = (double)sS[c] * inv - m[i] * m[k];
                var += (i == k ? w[i] * w[k] : 2.0 * w[i] * w[k]) * C;
                c++;
            }
        double rstd = rsqrt(var + 1e-5);
        float sc = (float)((double)G[tid] * rstd);
#pragma unroll
        for (int i = 0; i < 5; i++) { float wv = W[tid * 5 + i] * sc; sW[tid * 5 + i] = pk(wv, wv); }
        float bv = (float)(((double)B[tid] - mu) * rstd * (double)G[tid] + (double)Bt[tid]);
        sB[tid] = pk(bv, bv);
    }
    __syncthreads();
}

// ---------------- the whole net in one persistent kernel ----------------
__global__ void __launch_bounds__(NTHR, 1) net_kernel(
    const float* __restrict__ x,
    const float* __restrict__ lw,  const float* __restrict__ lb,
    const float* __restrict__ skw, const float* __restrict__ skb,
    const float* __restrict__ bng, const float* __restrict__ bnb,
    const float* __restrict__ l9w, const float* __restrict__ l9b,
    const float* __restrict__ b9g, const float* __restrict__ b9b,
    const float* __restrict__ l10w, const float* __restrict__ l10b,
    float* __restrict__ out)
{
    __shared__ ull sWi[25], sBi[5], sWj[25], sBj[5], sSkW[25];
    __shared__ float swr[NWARP][20];
    __shared__ float sS[20];

    const int tid = threadIdx.x;
    const int gt0 = blockIdx.x * NTHR + tid;
    const ull POL = mkpolicy_evict_last();
    const ull POLF = mkpolicy_evict_first();

    ull acc[20];

    // ---- pass 0: transpose x (AoS, streaming) -> g_Z (SoA, pinned) + stats(x)
#pragma unroll
    for (int q = 0; q < 20; q++) acc[q] = 0ull;
    for (int g = gt0; g < NGRP; g += TT) {
        const float4* p = (const float4*)(x + (size_t)20 * g);
        float4 A = load_x4_stream(p + 0, POLF), Bq = load_x4_stream(p + 1, POLF),
               Cq = load_x4_stream(p + 2, POLF), Dq = load_x4_stream(p + 3, POLF),
               Eq = load_x4_stream(p + 4, POLF);
        ull a[5], b[5];
        a[0] = pk(A.x,  Bq.y); a[1] = pk(A.y,  Bq.z); a[2] = pk(A.z,  Bq.w);
        a[3] = pk(A.w,  Cq.x); a[4] = pk(Bq.x, Cq.y);
        b[0] = pk(Cq.z, Dq.w); b[1] = pk(Cq.w, Eq.x); b[2] = pk(Dq.x, Eq.y);
        b[3] = pk(Dq.y, Eq.z); b[4] = pk(Dq.z, Eq.w);
        storeZ2(g, a, b, POL);
        st2(acc, a); st2(acc, b);
    }
    reduce_store(acc, 0, swr);
    grid_barrier();

    int slot = 0;
    for (int blk = 0; blk < 4; blk++) {
        const int li = 2 * blk, lj = li + 1;
        fold_affine(slot, 5, lw + li * 25, lb + li * 5, bng + li * 5, bnb + li * 5, sWi, sBi, sS);
        slot ^= 1;
        // ---- pass 1: stats(h), h not materialized
#pragma unroll
        for (int q = 0; q < 20; q++) acc[q] = 0ull;
        for (int g = gt0; g < NGRP; g += TT) {
            ull za[5], zb[5], ha[5], hb[5];
            loadZ2(g, za, zb, POL);
            aff5r(sWi, sBi, za, ha);
            aff5r(sWi, sBi, zb, hb);
            st2(acc, ha); st2(acc, hb);
        }
        reduce_store(acc, slot, swr);
        grid_barrier();
        fold_affine(slot, 5, lw + lj * 25, lb + lj * 5, bng + lj * 5, bnb + lj * 5, sWj, sBj, sS);
        if (tid < 25) { float w = skw[blk * 25 + tid]; sSkW[tid] = pk(w, w); }
        if (tid < 5)  { float sb = skb[blk * 5 + tid]; sBj[tid] = add2(sBj[tid], pk(sb, sb)); }
        __syncthreads();
        slot ^= 1;
        // ---- pass 2: z' = relu(foldaff_j(recompute h) + skip(z)), write Z, stats(z')
#pragma unroll
        for (int q = 0; q < 20; q++) acc[q] = 0ull;
        for (int g = gt0; g < NGRP; g += TT) {
            ull za[5], zb[5], ha[5], hb[5], na[5], nb[5];
            loadZ2(g, za, zb, POL);
            aff5r(sWi, sBi, za, ha);
            aff5r(sWi, sBi, zb, hb);
#pragma unroll
            for (int o = 0; o < 5; o++) {
                ull ta = sBj[o], tb = sBj[o];
#pragma unroll
                for (int i2 = 0; i2 < 5; i2++) {
                    ta = fma2(sWj[o * 5 + i2], ha[i2], ta);
                    tb = fma2(sWj[o * 5 + i2], hb[i2], tb);
                }
#pragma unroll
                for (int i2 = 0; i2 < 5; i2++) {
                    ta = fma2(sSkW[o * 5 + i2], za[i2], ta);
                    tb = fma2(sSkW[o * 5 + i2], zb[i2], tb);
                }
                na[o] = relu2(ta); nb[o] = relu2(tb);
            }
            storeZ2(g, na, nb, POL);
            st2(acc, na); st2(acc, nb);
        }
        reduce_store(acc, slot, swr);
        grid_barrier();
    }

    // ---- final: fold lin9+bn9 from stats(z), then out = lin10(relu(...))
    fold_affine(slot, 2, l9w, l9b, b9g, b9b, sWi, sBi, sS);
    const float w0 = l10w[0], w1 = l10w[1], c10 = l10b[0];
    const ull W0 = pk(w0, w0), W1 = pk(w1, w1), B10 = pk(c10, c10);
    for (int g = gt0; g < NGRP; g += TT) {
        ull za[5], zb[5];
        loadZ2(g, za, zb, POL);
        ull q0a = sBi[0], q1a = sBi[1], q0b = sBi[0], q1b = sBi[1];
#pragma unroll
        for (int i2 = 0; i2 < 5; i2++) {
            q0a = fma2(sWi[0 * 5 + i2], za[i2], q0a);
            q1a = fma2(sWi[1 * 5 + i2], za[i2], q1a);
            q0b = fma2(sWi[0 * 5 + i2], zb[i2], q0b);
            q1b = fma2(sWi[1 * 5 + i2], zb[i2], q1b);
        }
        q0a = relu2(q0a); q1a = relu2(q1a); q0b = relu2(q0b); q1b = relu2(q1b);
        ull oa = fma2(W0, q0a, fma2(W1, q1a, B10));
        ull ob = fma2(W0, q0b, fma2(W1, q1b, B10));
        float o0, o1, o2, o3; upk(oa, o0, o1); upk(ob, o2, o3);
        *(float4*)&out[4 * (size_t)g] = make_float4(o0, o1, o2, o3);
    }
}

extern "C" void kernel_launch(void* const* d_in, const int* in_sizes, int n_in,
                              void* d_out, int out_size) {
    (void)in_sizes; (void)n_in; (void)out_size;
    net_kernel<<<NBLK, NTHR>>>(
        (const float*)d_in[0],   // x
        (const float*)d_in[1],   // lins_w
        (const float*)d_in[2],   // lins_b
        (const float*)d_in[3],   // skips_w
        (const float*)d_in[4],   // skips_b
        (const float*)d_in[5],   // bn_g
        (const float*)d_in[6],   // bn_b
        (const float*)d_in[7],   // lin9_w
        (const float*)d_in[8],   // lin9_b
        (const float*)d_in[9],   // bn9_g
        (const float*)d_in[10],  // bn9_b
        (const float*)d_in[11],  // lin10_w
        (const float*)d_in[12],  // lin10_b
        (float*)d_out);
}